// round 16
// baseline (speedup 1.0000x reference)
#include <cuda_runtime.h>
#include <cuda_fp16.h>
#include <cstdint>

// ---------------------------------------------------------------------------
// ImplicitMeshDecoder via warp-level HMMA (mma.sync m16n8k16, fp16->fp32).
//   M = 524288 rows, H = 512.  Tile: 64 rows; 512 threads (16 warps),
//   warp grid 2m x 8n (warp tile 32x64); persistent grid = #SMs.
//   R16 (register-neutral, k-loop untouched):
//    - cold-start L1 prefetch: each layer's first B chunks prefetched in the
//      PRECEDING serial section (layer-0 / epi-1), turning the dependent
//      bc preloads from ~250cyc L2 trips into ~39cyc L1 hits.
//    - redundant trailing barrier removed (spart reuse is ordered by the
//      next tile's reduction barrier).
//   Batched silu (4 sigmoids / 1 rcp), persistent tiles, GMEM B fragments.
// ---------------------------------------------------------------------------

#define HDIM   512
#define MT     64
#define NT     512
#define PGRID  262144
#define BATCH  2
#define NTILE  ((BATCH * PGRID) / MT)    // 8192

// B fragment store: word (l, k16, wn, v, lane, e):
//   ng = 2v + (e>>1), half = e&1
//   n  = wn*64 + ng*8 + (lane>>2)
//   k0 = k16*16 + (lane&3)*2 + half*8
//   word = half2( W[k0][n], W[k0+1][n] )
// uint4 index: ((k16*8 + wn)*4 + v)*32 + lane   (per layer 32768 uint4 = 512KB)
__device__ float g_latb0[BATCH * HDIM];
__device__ __align__(16) uint4 g_wfrag[2 * 32768];

// ---- helpers ---------------------------------------------------------------
static __device__ __forceinline__ uint32_t smem_u32(const void* p) {
    uint32_t a;
    asm("{ .reg .u64 t; cvta.to.shared.u64 t, %1; cvt.u32.u64 %0, t; }"
        : "=r"(a) : "l"(p));
    return a;
}
// 4 silus, ONE rcp: r = rcp(abcd); 1/a = r*cd*b, etc.  4 EX2 + 1 RCP.
static __device__ __forceinline__ float4 silu4(float v0, float v1,
                                               float v2, float v3) {
    float a = 1.0f + __expf(-v0);
    float b = 1.0f + __expf(-v1);
    float c = 1.0f + __expf(-v2);
    float d = 1.0f + __expf(-v3);
    float ab = a * b, cd = c * d;
    float r;
    asm("rcp.approx.f32 %0, %1;" : "=f"(r) : "f"(ab * cd));
    float rab = r * cd, rcd = r * ab;
    return make_float4(v0 * (rab * b), v1 * (rab * a),
                       v2 * (rcd * d), v3 * (rcd * c));
}
// A tile (64 x 512 fp16, 1024B rows): byte for (r, k); XOR-permute 16B cols
static __device__ __forceinline__ uint32_t a_off(int r, int k) {
    return (uint32_t)(r * 1024) + (uint32_t)((((k >> 3) ^ (r & 7)) << 4))
         + (uint32_t)((k & 7) * 2);
}

#define LDSM4(r0, r1, r2, r3, addr)                                        \
    asm volatile("ldmatrix.sync.aligned.m8n8.x4.shared.b16 "               \
                 "{%0,%1,%2,%3}, [%4];"                                    \
                 : "=r"(r0), "=r"(r1), "=r"(r2), "=r"(r3) : "r"(addr))

#define MMA16816(d, a0, a1, a2, a3, b0, b1)                                \
    asm volatile("mma.sync.aligned.m16n8k16.row.col.f32.f16.f16.f32 "      \
                 "{%0,%1,%2,%3}, {%4,%5,%6,%7}, {%8,%9}, {%0,%1,%2,%3};"   \
                 : "+f"((d)[0]), "+f"((d)[1]), "+f"((d)[2]), "+f"((d)[3])  \
                 : "r"(a0), "r"(a1), "r"(a2), "r"(a3), "r"(b0), "r"(b1))

#define PF_L1(p) asm volatile("prefetch.global.L1 [%0];" :: "l"(p))

// ---- prep: latb0 = latent @ W0[:512] + b0  (one warp per output) -----------
__global__ void latb0_kernel(const float* __restrict__ lat,
                             const float* __restrict__ W0,
                             const float* __restrict__ b0) {
    int wg   = blockIdx.x * 8 + (threadIdx.x >> 5);   // 0..1023
    int lane = threadIdx.x & 31;
    int b = wg >> 9, h = wg & 511;
    const float* L = lat + b * HDIM;
    float s = 0.f;
#pragma unroll
    for (int d = lane; d < HDIM; d += 32)
        s = fmaf(L[d], W0[d * HDIM + h], s);
#pragma unroll
    for (int o = 16; o; o >>= 1) s += __shfl_xor_sync(0xffffffffu, s, o);
    if (lane == 0) g_latb0[b * HDIM + h] = s + b0[h];
}

// ---- prep: W1/W2 -> fp16 mma.sync B-fragment words -------------------------
// One thread per 4B word (262144 threads total).
__global__ void wprep_kernel(const float* __restrict__ W1,
                             const float* __restrict__ W2) {
    int idx  = blockIdx.x * blockDim.x + threadIdx.x;   // 0 .. 262143
    int e    = idx & 3;
    int lane = (idx >> 2) & 31;
    int v    = (idx >> 7) & 3;
    int wn   = (idx >> 9) & 7;
    int k16  = (idx >> 12) & 31;
    int l    = (idx >> 17) & 1;
    int ng   = 2 * v + (e >> 1);
    int half = e & 1;
    int n  = wn * 64 + ng * 8 + (lane >> 2);
    int k0 = k16 * 16 + (lane & 3) * 2 + half * 8;
    const float* W = l ? W2 : W1;
    __half2 w = __floats2half2_rn(W[k0 * HDIM + n], W[(k0 + 1) * HDIM + n]);
    ((__half2*)g_wfrag)[idx] = w;
}

// ---- main fused persistent kernel -------------------------------------------
__global__ __launch_bounds__(NT, 1)
void mlp_hmma_kernel(const float* __restrict__ W0,
                     const float* __restrict__ b1,
                     const float* __restrict__ b2,
                     const float* __restrict__ W3,
                     const float* __restrict__ b3,
                     float* __restrict__ out) {
    extern __shared__ char dyn[];
    uint32_t sbase = smem_u32(dyn);
    uint32_t s0 = (sbase + 1023u) & ~1023u;
    char* base = dyn + (s0 - sbase);

    char*  sA    = base;                       // 65536 (in-place across layers)
    float* sW3   = (float*)(base + 65536);     // 2048
    float* sB1   = (float*)(base + 67584);     // 2048
    float* sB2   = (float*)(base + 69632);     // 2048
    float* spart = (float*)(base + 71680);     // 2048 (64 rows x 8 wn)
    float* sb3   = (float*)(base + 73728);
    const uint32_t u_A = s0;

    const int tid  = threadIdx.x;
    const int lane = tid & 31, wid = tid >> 5;
    const int wm   = wid >> 3;                 // 0..1 : rows wm*32
    const int wn   = wid & 7;                  // 0..7 : cols wn*64

    // ---- one-time setup (hoisted out of the tile loop) ----
    sW3[tid] = W3[tid];
    sB1[tid] = b1[tid];
    sB2[tid] = b2[tid];
    if (tid == 0) *sb3 = b3[0];

    // layer-0 per-thread invariants (column-pair data, tile-independent)
    const float* Wc = W0 + (size_t)HDIM * HDIM;
    const int n0c = (tid & 255) * 2;           // col-pair
    const int rh  = tid >> 8;                  // rows rh*32 + i
    const float c00 = Wc[n0c],            c01 = Wc[n0c + 1];
    const float c10 = Wc[HDIM + n0c],     c11 = Wc[HDIM + n0c + 1];
    const float c20 = Wc[2 * HDIM + n0c], c21 = Wc[2 * HDIM + n0c + 1];
    const float lb0[2] = { g_latb0[n0c],        g_latb0[n0c + 1] };
    const float lb1[2] = { g_latb0[HDIM + n0c], g_latb0[HDIM + n0c + 1] };

    // per-lane ldmatrix addressing (invariant)
    const int x7 = lane & 7;                   // XOR term (== row&7 everywhere)
    const int ka = lane >> 4;                  // A k8-offset
    uint32_t aR[2];
#pragma unroll
    for (int i = 0; i < 2; i++)
        aR[i] = (uint32_t)((wm * 32 + i * 16 + (lane & 15)) * 1024);

    // per-warp B fragment stream bases (invariant across tiles)
    const uint4* wf0 = g_wfrag + (size_t)(wn * 4) * 32 + lane;  // layer 0
    const uint4* wf1 = wf0 + 32768;                             // layer 1

    // ---- persistent tile loop ----
#pragma unroll 1
    for (int tile = blockIdx.x; tile < NTILE; tile += gridDim.x) {
        const int m0 = tile * MT;

        // -------- layer 0: analytic coords + latent -> silu -> A --------
        // Within a tile (m0 % 64 == 0): x, y constant, z == row index r.
        {
            // warm L1 for layer-1 GEMM's first B chunks (cold-start cover)
#pragma unroll
            for (int v = 0; v < 4; v++) { PF_L1(wf0 + v * 32);
                                          PF_L1(wf0 + 1024 + v * 32); }
            const int bsel = m0 >> 18;
            const int p0   = m0 & (PGRID - 1);
            const float x = -1.2f + (float)(p0 >> 12)       * (2.4f / 63.0f);
            const float y = -1.2f + (float)((p0 >> 6) & 63) * (2.4f / 63.0f);
            const float base0 = fmaf(x, c00, fmaf(y, c10, bsel ? lb1[0] : lb0[0]));
            const float base1 = fmaf(x, c01, fmaf(y, c11, bsel ? lb1[1] : lb0[1]));
#pragma unroll 4
            for (int i = 0; i < 32; i += 2) {
                int r0 = rh * 32 + i;
                float z0 = -1.2f + (float)(r0)     * (2.4f / 63.0f);
                float z1 = -1.2f + (float)(r0 + 1) * (2.4f / 63.0f);
                float4 s = silu4(fmaf(z0, c20, base0), fmaf(z0, c21, base1),
                                 fmaf(z1, c20, base0), fmaf(z1, c21, base1));
                *(__half2*)(sA + a_off(r0,     n0c)) = __floats2half2_rn(s.x, s.y);
                *(__half2*)(sA + a_off(r0 + 1, n0c)) = __floats2half2_rn(s.z, s.w);
            }
        }
        __syncthreads();

        float pr[2][2];                        // layer-2 row partials
#pragma unroll
        for (int mg = 0; mg < 2; mg++) { pr[mg][0] = 0.f; pr[mg][1] = 0.f; }

#pragma unroll 1
        for (int l = 0; l < 2; l++) {
            // per-warp B fragment stream (both wm warps share it via L1)
            const uint4* wf = l ? wf1 : wf0;

            float acc[2][8][4];                // 32m x 64n per warp
#pragma unroll
            for (int mg = 0; mg < 2; mg++)
#pragma unroll
                for (int ng = 0; ng < 8; ng++)
#pragma unroll
                    for (int i = 0; i < 4; i++) acc[mg][ng][i] = 0.f;

            uint4 bc[4], bn[4];
#pragma unroll
            for (int v = 0; v < 4; v++)        // preload k16 = 0 (L1-warm)
                bc[v] = __ldg(wf + v * 32);

#pragma unroll 2
            for (int k16 = 0; k16 < 32; k16++) {
                if (k16 < 31) {                // prefetch next k16's fragments
                    const uint4* p = wf + (size_t)(k16 + 1) * 1024;  // 8*4*32
#pragma unroll
                    for (int v = 0; v < 4; v++) bn[v] = __ldg(p + v * 32);
                }
                const int kbA = k16 * 2 + ka;  // A k8-block index
                uint32_t ar[2][4];
#pragma unroll
                for (int i = 0; i < 2; i++)
                    LDSM4(ar[i][0], ar[i][1], ar[i][2], ar[i][3],
                          u_A + aR[i] + (uint32_t)((kbA ^ x7) << 4));
#pragma unroll
                for (int mg = 0; mg < 2; mg++)
#pragma unroll
                    for (int v = 0; v < 4; v++) {
                        MMA16816(acc[mg][2 * v],     ar[mg][0], ar[mg][1],
                                 ar[mg][2], ar[mg][3], bc[v].x, bc[v].y);
                        MMA16816(acc[mg][2 * v + 1], ar[mg][0], ar[mg][1],
                                 ar[mg][2], ar[mg][3], bc[v].z, bc[v].w);
                    }
#pragma unroll
                for (int v = 0; v < 4; v++) bc[v] = bn[v];
            }

            // -------- epilogue (adds layer bias, then batched silu) --------
            if (l == 0) {
                __syncthreads();   // all warps done reading A -> overwrite ok
                // warm L1 for layer-2 GEMM's first B chunks
#pragma unroll
                for (int v = 0; v < 4; v++) { PF_L1(wf1 + v * 32);
                                              PF_L1(wf1 + 1024 + v * 32); }
#pragma unroll
                for (int mg = 0; mg < 2; mg++) {
                    int rbase = wm * 32 + mg * 16 + (lane >> 2);
#pragma unroll
                    for (int ng = 0; ng < 8; ng++) {
                        int nc = wn * 64 + ng * 8 + 2 * (lane & 3);
                        float bb0 = sB1[nc], bb1 = sB1[nc + 1];
                        float4 s = silu4(acc[mg][ng][0] + bb0,
                                         acc[mg][ng][1] + bb1,
                                         acc[mg][ng][2] + bb0,
                                         acc[mg][ng][3] + bb1);
                        *(__half2*)(sA + a_off(rbase, nc))
                            = __floats2half2_rn(s.x, s.y);
                        *(__half2*)(sA + a_off(rbase + 8, nc))
                            = __floats2half2_rn(s.z, s.w);
                    }
                }
                __syncthreads();   // A rewritten -> visible to layer-2 reads
            } else {
                // bias + batched silu + W3 dot folded into row partials
#pragma unroll
                for (int mg = 0; mg < 2; mg++)
#pragma unroll
                    for (int ng = 0; ng < 8; ng++) {
                        int nc = wn * 64 + ng * 8 + 2 * (lane & 3);
                        float bb0 = sB2[nc], bb1 = sB2[nc + 1];
                        float w0 = sW3[nc],  w1 = sW3[nc + 1];
                        float4 s = silu4(acc[mg][ng][0] + bb0,
                                         acc[mg][ng][1] + bb1,
                                         acc[mg][ng][2] + bb0,
                                         acc[mg][ng][3] + bb1);
                        pr[mg][0] = fmaf(s.x, w0, pr[mg][0]);
                        pr[mg][0] = fmaf(s.y, w1, pr[mg][0]);
                        pr[mg][1] = fmaf(s.z, w0, pr[mg][1]);
                        pr[mg][1] = fmaf(s.w, w1, pr[mg][1]);
                    }
            }
        }

        // -------- final reduction: lanes (cols) -> warps (wn) -> rows --------
#pragma unroll
        for (int mg = 0; mg < 2; mg++)
#pragma unroll
            for (int h = 0; h < 2; h++) {
                float v = pr[mg][h];
                v += __shfl_xor_sync(0xffffffffu, v, 1);
                v += __shfl_xor_sync(0xffffffffu, v, 2);
                if ((lane & 3) == 0) {
                    int r = wm * 32 + mg * 16 + (lane >> 2) + 8 * h;
                    spart[r * 8 + wn] = v;
                }
            }
        __syncthreads();
        if (tid < MT) {
            float s = *sb3;
#pragma unroll
            for (int w = 0; w < 8; w++) s += spart[tid * 8 + w];
            out[m0 + tid] = s;
        }
        // NOTE: no trailing barrier — spart's next write is behind the next
        // tile's reduction __syncthreads(); layer-0's sA writes are behind
        // the layer-0 barrier.  (The post-out barrier was redundant.)
    }
}

// ---------------------------------------------------------------------------
extern "C" void kernel_launch(void* const* d_in, const int* in_sizes, int n_in,
                              void* d_out, int out_size) {
    const float* lat = (const float*)d_in[0];
    const float* W0  = (const float*)d_in[1];
    const float* b0  = (const float*)d_in[2];
    const float* W1  = (const float*)d_in[3];
    const float* b1  = (const float*)d_in[4];
    const float* W2  = (const float*)d_in[5];
    const float* b2  = (const float*)d_in[6];
    const float* W3  = (const float*)d_in[7];
    const float* b3  = (const float*)d_in[8];
    float* out = (float*)d_out;

    latb0_kernel<<<128, 256>>>(lat, W0, b0);
    wprep_kernel<<<512, 512>>>(W1, W2);

    static int nsm = 0;                 // host-side query, graph-capture safe
    if (nsm == 0) {
        cudaDeviceGetAttribute(&nsm, cudaDevAttrMultiProcessorCount, 0);
        if (nsm <= 0) nsm = 148;
    }

    size_t smem = 1024 + 73728 + 64;   // slack + A(64K) + scalars
    cudaFuncSetAttribute(mlp_hmma_kernel,
                         cudaFuncAttributeMaxDynamicSharedMemorySize, (int)smem);
    mlp_hmma_kernel<<<nsm, NT, smem>>>(W0, b1, b2, W3, b3, out);
}

// round 17
// speedup vs baseline: 1.0194x; 1.0194x over previous
#include <cuda_runtime.h>
#include <cuda_fp16.h>
#include <cstdint>

// ---------------------------------------------------------------------------
// ImplicitMeshDecoder via warp-level HMMA (mma.sync m16n8k16, fp16->fp32).
//   M = 524288 rows, H = 512.  Tile: 64 rows; 512 threads (16 warps),
//   warp grid 2m x 8n (warp tile 32x64); persistent grid = #SMs.
//   R17 (barrier surgery, register-neutral, k-loop untouched, base=R15):
//    - ping-pong A buffer (sA[0]/sA[1]): next tile's layer-0 writes can't
//      collide with straggler layer-2 reads -> tile-end barriers removed.
//    - deferred out-write: tile t's result is written at the START of tile
//      t+1 (after the layer-0 barrier), overlapping STG + reduction with
//      the next GEMM.  Barriers: 5 -> 3 per tile.
//   Batched silu (4 sigmoids / 1 rcp), persistent tiles, GMEM B fragments.
// ---------------------------------------------------------------------------

#define HDIM   512
#define MT     64
#define NT     512
#define PGRID  262144
#define BATCH  2
#define NTILE  ((BATCH * PGRID) / MT)    // 8192

// B fragment store: word (l, k16, wn, v, lane, e):
//   ng = 2v + (e>>1), half = e&1
//   n  = wn*64 + ng*8 + (lane>>2)
//   k0 = k16*16 + (lane&3)*2 + half*8
//   word = half2( W[k0][n], W[k0+1][n] )
// uint4 index: ((k16*8 + wn)*4 + v)*32 + lane   (per layer 32768 uint4 = 512KB)
__device__ float g_latb0[BATCH * HDIM];
__device__ __align__(16) uint4 g_wfrag[2 * 32768];

// ---- helpers ---------------------------------------------------------------
static __device__ __forceinline__ uint32_t smem_u32(const void* p) {
    uint32_t a;
    asm("{ .reg .u64 t; cvta.to.shared.u64 t, %1; cvt.u32.u64 %0, t; }"
        : "=r"(a) : "l"(p));
    return a;
}
// 4 silus, ONE rcp: r = rcp(abcd); 1/a = r*cd*b, etc.  4 EX2 + 1 RCP.
static __device__ __forceinline__ float4 silu4(float v0, float v1,
                                               float v2, float v3) {
    float a = 1.0f + __expf(-v0);
    float b = 1.0f + __expf(-v1);
    float c = 1.0f + __expf(-v2);
    float d = 1.0f + __expf(-v3);
    float ab = a * b, cd = c * d;
    float r;
    asm("rcp.approx.f32 %0, %1;" : "=f"(r) : "f"(ab * cd));
    float rab = r * cd, rcd = r * ab;
    return make_float4(v0 * (rab * b), v1 * (rab * a),
                       v2 * (rcd * d), v3 * (rcd * c));
}
// A tile (64 x 512 fp16, 1024B rows): byte for (r, k); XOR-permute 16B cols
static __device__ __forceinline__ uint32_t a_off(int r, int k) {
    return (uint32_t)(r * 1024) + (uint32_t)((((k >> 3) ^ (r & 7)) << 4))
         + (uint32_t)((k & 7) * 2);
}

#define LDSM4(r0, r1, r2, r3, addr)                                        \
    asm volatile("ldmatrix.sync.aligned.m8n8.x4.shared.b16 "               \
                 "{%0,%1,%2,%3}, [%4];"                                    \
                 : "=r"(r0), "=r"(r1), "=r"(r2), "=r"(r3) : "r"(addr))

#define MMA16816(d, a0, a1, a2, a3, b0, b1)                                \
    asm volatile("mma.sync.aligned.m16n8k16.row.col.f32.f16.f16.f32 "      \
                 "{%0,%1,%2,%3}, {%4,%5,%6,%7}, {%8,%9}, {%0,%1,%2,%3};"   \
                 : "+f"((d)[0]), "+f"((d)[1]), "+f"((d)[2]), "+f"((d)[3])  \
                 : "r"(a0), "r"(a1), "r"(a2), "r"(a3), "r"(b0), "r"(b1))

// ---- prep: latb0 = latent @ W0[:512] + b0  (one warp per output) -----------
__global__ void latb0_kernel(const float* __restrict__ lat,
                             const float* __restrict__ W0,
                             const float* __restrict__ b0) {
    int wg   = blockIdx.x * 8 + (threadIdx.x >> 5);   // 0..1023
    int lane = threadIdx.x & 31;
    int b = wg >> 9, h = wg & 511;
    const float* L = lat + b * HDIM;
    float s = 0.f;
#pragma unroll
    for (int d = lane; d < HDIM; d += 32)
        s = fmaf(L[d], W0[d * HDIM + h], s);
#pragma unroll
    for (int o = 16; o; o >>= 1) s += __shfl_xor_sync(0xffffffffu, s, o);
    if (lane == 0) g_latb0[b * HDIM + h] = s + b0[h];
}

// ---- prep: W1/W2 -> fp16 mma.sync B-fragment words -------------------------
// One thread per 4B word (262144 threads total).
__global__ void wprep_kernel(const float* __restrict__ W1,
                             const float* __restrict__ W2) {
    int idx  = blockIdx.x * blockDim.x + threadIdx.x;   // 0 .. 262143
    int e    = idx & 3;
    int lane = (idx >> 2) & 31;
    int v    = (idx >> 7) & 3;
    int wn   = (idx >> 9) & 7;
    int k16  = (idx >> 12) & 31;
    int l    = (idx >> 17) & 1;
    int ng   = 2 * v + (e >> 1);
    int half = e & 1;
    int n  = wn * 64 + ng * 8 + (lane >> 2);
    int k0 = k16 * 16 + (lane & 3) * 2 + half * 8;
    const float* W = l ? W2 : W1;
    __half2 w = __floats2half2_rn(W[k0 * HDIM + n], W[(k0 + 1) * HDIM + n]);
    ((__half2*)g_wfrag)[idx] = w;
}

// ---- main fused persistent kernel -------------------------------------------
__global__ __launch_bounds__(NT, 1)
void mlp_hmma_kernel(const float* __restrict__ W0,
                     const float* __restrict__ b1,
                     const float* __restrict__ b2,
                     const float* __restrict__ W3,
                     const float* __restrict__ b3,
                     float* __restrict__ out) {
    extern __shared__ char dyn[];
    uint32_t sbase = smem_u32(dyn);
    uint32_t s0 = (sbase + 1023u) & ~1023u;
    char* base = dyn + (s0 - sbase);

    // sA ping-pong: [0, 64K) and [64K, 128K)
    float* sW3   = (float*)(base + 131072);    // 2048
    float* sB1   = (float*)(base + 133120);    // 2048
    float* sB2   = (float*)(base + 135168);    // 2048
    float* spart = (float*)(base + 137216);    // 2048 (64 rows x 8 wn)
    float* sb3   = (float*)(base + 139264);

    const int tid  = threadIdx.x;
    const int lane = tid & 31, wid = tid >> 5;
    const int wm   = wid >> 3;                 // 0..1 : rows wm*32
    const int wn   = wid & 7;                  // 0..7 : cols wn*64

    // ---- one-time setup (hoisted out of the tile loop) ----
    sW3[tid] = W3[tid];
    sB1[tid] = b1[tid];
    sB2[tid] = b2[tid];
    if (tid == 0) *sb3 = b3[0];

    // layer-0 per-thread invariants (column-pair data, tile-independent)
    const float* Wc = W0 + (size_t)HDIM * HDIM;
    const int n0c = (tid & 255) * 2;           // col-pair
    const int rh  = tid >> 8;                  // rows rh*32 + i
    const float c00 = Wc[n0c],            c01 = Wc[n0c + 1];
    const float c10 = Wc[HDIM + n0c],     c11 = Wc[HDIM + n0c + 1];
    const float c20 = Wc[2 * HDIM + n0c], c21 = Wc[2 * HDIM + n0c + 1];
    const float lb0[2] = { g_latb0[n0c],        g_latb0[n0c + 1] };
    const float lb1[2] = { g_latb0[HDIM + n0c], g_latb0[HDIM + n0c + 1] };

    // per-lane ldmatrix addressing (invariant)
    const int x7 = lane & 7;                   // XOR term (== row&7 everywhere)
    const int ka = lane >> 4;                  // A k8-offset
    uint32_t aR[2];
#pragma unroll
    for (int i = 0; i < 2; i++)
        aR[i] = (uint32_t)((wm * 32 + i * 16 + (lane & 15)) * 1024);

    int prev_m0 = -1;                          // deferred out-write cursor
    int pp = 0;                                // A-buffer parity

    // ---- persistent tile loop ----
#pragma unroll 1
    for (int tile = blockIdx.x; tile < NTILE; tile += gridDim.x) {
        const int m0 = tile * MT;
        char*    sA  = base + pp * 65536;
        const uint32_t u_A = s0 + (uint32_t)(pp * 65536);

        // -------- layer 0: analytic coords + latent -> silu -> A[pp] ------
        // (no barrier needed before: stragglers read A[1-pp])
        {
            const int bsel = m0 >> 18;
            const int p0   = m0 & (PGRID - 1);
            const float x = -1.2f + (float)(p0 >> 12)       * (2.4f / 63.0f);
            const float y = -1.2f + (float)((p0 >> 6) & 63) * (2.4f / 63.0f);
            const float base0 = fmaf(x, c00, fmaf(y, c10, bsel ? lb1[0] : lb0[0]));
            const float base1 = fmaf(x, c01, fmaf(y, c11, bsel ? lb1[1] : lb0[1]));
#pragma unroll 4
            for (int i = 0; i < 32; i += 2) {
                int r0 = rh * 32 + i;
                float z0 = -1.2f + (float)(r0)     * (2.4f / 63.0f);
                float z1 = -1.2f + (float)(r0 + 1) * (2.4f / 63.0f);
                float4 s = silu4(fmaf(z0, c20, base0), fmaf(z0, c21, base1),
                                 fmaf(z1, c20, base0), fmaf(z1, c21, base1));
                *(__half2*)(sA + a_off(r0,     n0c)) = __floats2half2_rn(s.x, s.y);
                *(__half2*)(sA + a_off(r0 + 1, n0c)) = __floats2half2_rn(s.z, s.w);
            }
        }
        __syncthreads();    // B1: A[pp] ready; prev tile's spart writes ready

        // deferred out-write for the previous tile (overlaps next GEMM)
        if (prev_m0 >= 0 && tid < MT) {
            float s = *sb3;
#pragma unroll
            for (int w = 0; w < 8; w++) s += spart[tid * 8 + w];
            out[prev_m0 + tid] = s;
        }

        float pr[2][2];                        // layer-2 row partials
#pragma unroll
        for (int mg = 0; mg < 2; mg++) { pr[mg][0] = 0.f; pr[mg][1] = 0.f; }

#pragma unroll 1
        for (int l = 0; l < 2; l++) {
            // per-warp B fragment stream (both wm warps share it via L1)
            const uint4* wf = g_wfrag + (size_t)l * 32768
                            + (size_t)(wn * 4) * 32 + lane;   // k16=0, v=0

            float acc[2][8][4];                // 32m x 64n per warp
#pragma unroll
            for (int mg = 0; mg < 2; mg++)
#pragma unroll
                for (int ng = 0; ng < 8; ng++)
#pragma unroll
                    for (int i = 0; i < 4; i++) acc[mg][ng][i] = 0.f;

            uint4 bc[4], bn[4];
#pragma unroll
            for (int v = 0; v < 4; v++)        // preload k16 = 0
                bc[v] = __ldg(wf + v * 32);

#pragma unroll 2
            for (int k16 = 0; k16 < 32; k16++) {
                if (k16 < 31) {                // prefetch next k16's fragments
                    const uint4* p = wf + (size_t)(k16 + 1) * 1024;  // 8*4*32
#pragma unroll
                    for (int v = 0; v < 4; v++) bn[v] = __ldg(p + v * 32);
                }
                const int kbA = k16 * 2 + ka;  // A k8-block index
                uint32_t ar[2][4];
#pragma unroll
                for (int i = 0; i < 2; i++)
                    LDSM4(ar[i][0], ar[i][1], ar[i][2], ar[i][3],
                          u_A + aR[i] + (uint32_t)((kbA ^ x7) << 4));
#pragma unroll
                for (int mg = 0; mg < 2; mg++)
#pragma unroll
                    for (int v = 0; v < 4; v++) {
                        MMA16816(acc[mg][2 * v],     ar[mg][0], ar[mg][1],
                                 ar[mg][2], ar[mg][3], bc[v].x, bc[v].y);
                        MMA16816(acc[mg][2 * v + 1], ar[mg][0], ar[mg][1],
                                 ar[mg][2], ar[mg][3], bc[v].z, bc[v].w);
                    }
#pragma unroll
                for (int v = 0; v < 4; v++) bc[v] = bn[v];
            }

            // -------- epilogue (adds layer bias, then batched silu) --------
            if (l == 0) {
                __syncthreads();   // B2: all warps done reading A[pp]
#pragma unroll
                for (int mg = 0; mg < 2; mg++) {
                    int rbase = wm * 32 + mg * 16 + (lane >> 2);
#pragma unroll
                    for (int ng = 0; ng < 8; ng++) {
                        int nc = wn * 64 + ng * 8 + 2 * (lane & 3);
                        float bb0 = sB1[nc], bb1 = sB1[nc + 1];
                        float4 s = silu4(acc[mg][ng][0] + bb0,
                                         acc[mg][ng][1] + bb1,
                                         acc[mg][ng][2] + bb0,
                                         acc[mg][ng][3] + bb1);
                        *(__half2*)(sA + a_off(rbase, nc))
                            = __floats2half2_rn(s.x, s.y);
                        *(__half2*)(sA + a_off(rbase + 8, nc))
                            = __floats2half2_rn(s.z, s.w);
                    }
                }
                __syncthreads();   // B3: A[pp] rewritten -> layer-2 reads
            } else {
                // bias + batched silu + W3 dot folded into row partials
#pragma unroll
                for (int mg = 0; mg < 2; mg++)
#pragma unroll
                    for (int ng = 0; ng < 8; ng++) {
                        int nc = wn * 64 + ng * 8 + 2 * (lane & 3);
                        float bb0 = sB2[nc], bb1 = sB2[nc + 1];
                        float w0 = sW3[nc],  w1 = sW3[nc + 1];
                        float4 s = silu4(acc[mg][ng][0] + bb0,
                                         acc[mg][ng][1] + bb1,
                                         acc[mg][ng][2] + bb0,
                                         acc[mg][ng][3] + bb1);
                        pr[mg][0] = fmaf(s.x, w0, pr[mg][0]);
                        pr[mg][0] = fmaf(s.y, w1, pr[mg][0]);
                        pr[mg][1] = fmaf(s.z, w0, pr[mg][1]);
                        pr[mg][1] = fmaf(s.w, w1, pr[mg][1]);
                    }
            }
        }

        // -------- reduction: lanes -> spart (consumed at next tile's B1) ----
        // spart reads for prev tile finished before B2; safe to overwrite now.
#pragma unroll
        for (int mg = 0; mg < 2; mg++)
#pragma unroll
            for (int h = 0; h < 2; h++) {
                float v = pr[mg][h];
                v += __shfl_xor_sync(0xffffffffu, v, 1);
                v += __shfl_xor_sync(0xffffffffu, v, 2);
                if ((lane & 3) == 0) {
                    int r = wm * 32 + mg * 16 + (lane >> 2) + 8 * h;
                    spart[r * 8 + wn] = v;
                }
            }
        prev_m0 = m0;
        pp ^= 1;
    }

    // ---- drain: final tile's out-write ----
    __syncthreads();
    if (prev_m0 >= 0 && tid < MT) {
        float s = *sb3;
#pragma unroll
        for (int w = 0; w < 8; w++) s += spart[tid * 8 + w];
        out[prev_m0 + tid] = s;
    }
}

// ---------------------------------------------------------------------------
extern "C" void kernel_launch(void* const* d_in, const int* in_sizes, int n_in,
                              void* d_out, int out_size) {
    const float* lat = (const float*)d_in[0];
    const float* W0  = (const float*)d_in[1];
    const float* b0  = (const float*)d_in[2];
    const float* W1  = (const float*)d_in[3];
    const float* b1  = (const float*)d_in[4];
    const float* W2  = (const float*)d_in[5];
    const float* b2  = (const float*)d_in[6];
    const float* W3  = (const float*)d_in[7];
    const float* b3  = (const float*)d_in[8];
    float* out = (float*)d_out;

    latb0_kernel<<<128, 256>>>(lat, W0, b0);
    wprep_kernel<<<512, 512>>>(W1, W2);

    static int nsm = 0;                 // host-side query, graph-capture safe
    if (nsm == 0) {
        cudaDeviceGetAttribute(&nsm, cudaDevAttrMultiProcessorCount, 0);
        if (nsm <= 0) nsm = 148;
    }

    size_t smem = 1024 + 139328 + 64;   // slack + 2xA(64K) + scalars
    cudaFuncSetAttribute(mlp_hmma_kernel,
                         cudaFuncAttributeMaxDynamicSharedMemorySize, (int)smem);
    mlp_hmma_kernel<<<nsm, NT, smem>>>(W0, b1, b2, W3, b3, out);
}